// round 17
// baseline (speedup 1.0000x reference)
#include <cuda_runtime.h>
#include <cstdint>

// Skinny GEMM via mma.sync tf32: BOTH operands latency-covered.
// C[65536,40] = embs[65536,1024] @ W^T, W = [W_status(5); W_flight(30); 0pad]
// R17 thesis: in every prior variant exactly one operand's global latency was
// exposed in-iteration (A ring covered A but B-LDG was consumed immediately;
// R14 covered B but A-LDG was consumed immediately) -> identical ~78us
// equilibrium. Here: A = 5-slot per-warp cp.async ring; B = 5 smem buffers
// staged from fragment-packed Wpack (512B contiguous per (kb,nt) tile).
// One commit group per iter carries A(kb+4)+B(kb+4); wait<3> + 1 barrier per
// k16. Steady-state mainloop touches only smem (LDS, conflict-free).
// Raw fp32 bits as tf32 (RZ truncate), bias cancelled by corr in epilogue.

#define EMB    1024
#define NS     5
#define NF     30
#define NL     35
#define OUTC   63
#define BM     128
#define LSTR   41
#define NTH    128
#define NKB    (EMB / 16)   // 64 k16 blocks
#define SLOTS  5            // ring slots (4 groups in flight)

// A ring: per warp 5 slots x 128 uint4 = 10240B; 4 warps = 40960B
#define ASLOT_B   2048
#define AWARP_B   (SLOTS * ASLOT_B)
#define BOFF      (4 * AWARP_B)          // 40960
#define BBUF_B    2560                   // 160 uint4 per kb chunk
#define SMEM_B    (BOFF + SLOTS * BBUF_B)  // 53760

// fragment-packed B: tile (kb,nt) = 32 lanes x 16B contiguous
__device__ float Wpack[NKB * 5 * 32 * 4];   // 160KB

__global__ void pack_w_kernel(const float* __restrict__ Ws,
                              const float* __restrict__ Wf) {
    int i = blockIdx.x * blockDim.x + threadIdx.x;   // 40960 floats
    if (i < NKB * 5 * 32 * 4) {
        int e    = i & 3;
        int cell = i >> 2;
        int t    = cell & 3;
        int g    = (cell >> 2) & 7;
        int rest = cell >> 5;
        int nt   = rest % 5;
        int kb   = rest / 5;
        int row  = nt * 8 + g;
        int col  = kb * 16 + t * 4 + e;
        float v = 0.0f;
        if (row < NS)      v = Ws[row * EMB + col];
        else if (row < NL) v = Wf[(row - NS) * EMB + col];
        Wpack[i] = v;
    }
}

__device__ __forceinline__ void mma8(float* c, const uint32_t* a, const uint32_t* b) {
    asm volatile(
        "mma.sync.aligned.m16n8k8.row.col.f32.tf32.tf32.f32 "
        "{%0,%1,%2,%3}, {%4,%5,%6,%7}, {%8,%9}, {%0,%1,%2,%3};"
        : "+f"(c[0]), "+f"(c[1]), "+f"(c[2]), "+f"(c[3])
        : "r"(a[0]), "r"(a[1]), "r"(a[2]), "r"(a[3]), "r"(b[0]), "r"(b[1]));
}
__device__ __forceinline__ void cp16s(uint32_t dst, const void* src) {
    asm volatile("cp.async.cg.shared.global [%0], [%1], 16;" :: "r"(dst), "l"(src));
}
__device__ __forceinline__ void cp_commit() { asm volatile("cp.async.commit_group;"); }
template<int N> __device__ __forceinline__ void cp_wait() {
    asm volatile("cp.async.wait_group %0;" :: "n"(N));
}
__device__ __forceinline__ uint4 lds128(uint32_t a) {
    uint4 v;
    asm volatile("ld.shared.v4.u32 {%0,%1,%2,%3}, [%4];"
                 : "=r"(v.x), "=r"(v.y), "=r"(v.z), "=r"(v.w) : "r"(a));
    return v;
}

extern __shared__ __align__(16) char sraw[];

__global__ __launch_bounds__(NTH, 4) void aux2_dual_kernel(
    const float* __restrict__ embs,
    const float* __restrict__ b_status,
    const float* __restrict__ b_flight,
    float* __restrict__ out,
    int ntok)
{
    const int tid  = threadIdx.x;
    const int wid  = tid >> 5;
    const int lane = tid & 31;
    const int g    = lane >> 2;     // 0..7
    const int t    = lane & 3;      // 0..3
    const long tokw = (long)blockIdx.x * BM + wid * 32;

    const uint32_t sbase = (uint32_t)__cvta_generic_to_shared(sraw);
    const uint32_t aring = sbase + (uint32_t)wid * AWARP_B;
    const uint32_t bbase = sbase + BOFF;

    // per-lane global A pointers: row tokw + r*8 + g, col 4t (advance 16/kb)
    const float* gptr[4];
#pragma unroll
    for (int r = 0; r < 4; ++r)
        gptr[r] = embs + (tokw + r * 8 + g) * EMB + 4 * t;

    const uint4* Wp = reinterpret_cast<const uint4*>(Wpack);

    // stage helpers -------------------------------------------------------
    auto stageA = [&](int slot, int kb) {
#pragma unroll
        for (int r = 0; r < 4; ++r)
            cp16s(aring + (uint32_t)(slot * ASLOT_B) + (uint32_t)(r * 32 + lane) * 16u,
                  gptr[r] + kb * 16);
    };
    auto stageB = [&](int buf, int kb) {
        const uint4* src = Wp + kb * 160;
        uint32_t dst = bbase + (uint32_t)(buf * BBUF_B);
        cp16s(dst + (uint32_t)tid * 16u, src + tid);
        if (tid < 32)
            cp16s(dst + (uint32_t)(128 + tid) * 16u, src + 128 + tid);
    };

    float acc[2][5][4];
#pragma unroll
    for (int mt = 0; mt < 2; ++mt)
#pragma unroll
        for (int nt = 0; nt < 5; ++nt)
#pragma unroll
            for (int i = 0; i < 4; ++i) acc[mt][nt][i] = 0.0f;

    // ---- prologue: groups for data 0..3 ----
#pragma unroll
    for (int s = 0; s < 4; ++s) {
        stageA(s, s);
        stageB(s, s);
        cp_commit();
    }

    // ---- mainloop: wait -> sync -> stage(kb+4) -> commit -> consume ----
    int sr = 0;   // read slot  = kb % 5
    int sp = 4;   // stage slot = (kb+4) % 5
#pragma unroll 1
    for (int kb = 0; kb < NKB; ++kb) {
        cp_wait<3>();          // group (data kb) complete
        __syncthreads();       // B buffer sr visible CTA-wide

        if (kb + 4 < NKB) {
            stageA(sp, kb + 4);
            stageB(sp, kb + 4);
        }
        cp_commit();           // unconditional: uniform group accounting

        // consume A slot sr (LDS.128 x4, conflict-free)
        uint4 v[4];
        {
            uint32_t sa = aring + (uint32_t)(sr * ASLOT_B) + (uint32_t)lane * 16u;
#pragma unroll
            for (int r = 0; r < 4; ++r)
                v[r] = lds128(sa + (uint32_t)(r * 32) * 16u);
        }

        uint32_t af0[2][4] = {
            { v[0].x, v[1].x, v[0].y, v[1].y },
            { v[2].x, v[3].x, v[2].y, v[3].y } };
        uint32_t af1[2][4] = {
            { v[0].z, v[1].z, v[0].w, v[1].w },
            { v[2].z, v[3].z, v[2].w, v[3].w } };

        // consume B buffer sr (5 x LDS.128, lane-consecutive, conflict-free)
        uint32_t bb = bbase + (uint32_t)(sr * BBUF_B) + (uint32_t)lane * 16u;
#pragma unroll
        for (int nt = 0; nt < 5; ++nt) {
            uint4 b = lds128(bb + (uint32_t)(nt * 32) * 16u);
            uint32_t bf0[2] = { b.x, b.y };
            uint32_t bf1[2] = { b.z, b.w };
#pragma unroll
            for (int mt = 0; mt < 2; ++mt) {
                mma8(acc[mt][nt], af0[mt], bf0);
                mma8(acc[mt][nt], af1[mt], bf1);
            }
        }

        sr = (sr == SLOTS - 1) ? 0 : sr + 1;
        sp = (sp == SLOTS - 1) ? 0 : sp + 1;
    }

    cp_wait<0>();
    __syncthreads();          // buffers dead; alias as logits

    // ---- epilogue: fragments -> logits smem ----
    float* Ls = reinterpret_cast<float*>(sraw);   // 21KB < 53.7KB
#pragma unroll
    for (int mt = 0; mt < 2; ++mt)
#pragma unroll
        for (int nt = 0; nt < 5; ++nt) {
            int r0 = wid * 32 + mt * 16 + g;
            int cc = nt * 8 + t * 2;
            if (cc < NL) {
                Ls[r0 * LSTR + cc]       = acc[mt][nt][0];
                Ls[(r0 + 8) * LSTR + cc] = acc[mt][nt][2];
            }
            if (cc + 1 < NL) {
                Ls[r0 * LSTR + cc + 1]       = acc[mt][nt][1];
                Ls[(r0 + 8) * LSTR + cc + 1] = acc[mt][nt][3];
            }
        }
    __syncthreads();

    // ---- per-thread dual softmax + store (thread tid = token) ----
    {
        const float corr = 1.000677f;   // tf32 RZ truncation bias compensation
        float sl[NS], fl[NF];
#pragma unroll
        for (int n = 0; n < NS; ++n) sl[n] = Ls[tid * LSTR + n] * corr + b_status[n];
#pragma unroll
        for (int n = 0; n < NF; ++n) fl[n] = Ls[tid * LSTR + NS + n] * corr + b_flight[n];

        float smax = sl[0];
#pragma unroll
        for (int n = 1; n < NS; ++n) smax = fmaxf(smax, sl[n]);
        float ssum = 0.f;
#pragma unroll
        for (int n = 0; n < NS; ++n) { sl[n] = __expf(sl[n] - smax); ssum += sl[n]; }
        float sinv = 1.f / ssum;
#pragma unroll
        for (int n = 0; n < NS; ++n) sl[n] *= sinv;

        float fm = fl[0];
#pragma unroll
        for (int n = 1; n < NF; ++n) fm = fmaxf(fm, fl[n]);
        float fsum = 0.f;
#pragma unroll
        for (int n = 0; n < NF; ++n) { fl[n] = __expf(fl[n] - fm); fsum += fl[n]; }
        float finv = 1.f / fsum;
#pragma unroll
        for (int n = 0; n < NF; ++n) fl[n] *= finv;

        const float book = sl[4], change = sl[3];
        long token = (long)blockIdx.x * BM + tid;
        if (token < ntok) {
            float* op = out + token * (long)OUTC;
            op[0] = sl[0];
            op[1] = sl[2];
            op[2] = sl[1];
#pragma unroll
            for (int j = 0; j < NF; ++j) {
                op[3 + j]  = book   * fl[j];
                op[33 + j] = change * fl[j];
            }
        }
    }
}

extern "C" void kernel_launch(void* const* d_in, const int* in_sizes, int n_in,
                              void* d_out, int out_size) {
    const float* embs     = (const float*)d_in[0];
    const float* W_status = (const float*)d_in[1];
    const float* b_status = (const float*)d_in[2];
    const float* W_flight = (const float*)d_in[3];
    const float* b_flight = (const float*)d_in[4];
    float* out = (float*)d_out;

    cudaFuncSetAttribute(aux2_dual_kernel,
                         cudaFuncAttributeMaxDynamicSharedMemorySize, SMEM_B);

    // pack weights into fragment-ordered __device__ array (capturable)
    pack_w_kernel<<<(NKB * 5 * 32 * 4 + 255) / 256, 256>>>(W_status, W_flight);

    int ntok = in_sizes[0] / EMB;   // 65536
    int blocks = ntok / BM;         // 512
    aux2_dual_kernel<<<blocks, NTH, SMEM_B>>>(embs, b_status, b_flight, out, ntok);
}